// round 7
// baseline (speedup 1.0000x reference)
#include <cuda_runtime.h>
#include <stdint.h>
#include <math.h>

#define BATCH   8
#define NANCH   76725
#define NROWS   (BATCH*NANCH)
#define NC      80
#define NF      84
#define KMAX    100
#define CAP     1024
#define NPAIR   (BATCH*NC)
#define FLOOR_LOGIT 2.5f
#define SCORE_TH 0.05f
#define IOU_THR 0.5f
#define CSH     5

typedef unsigned long long u64;
typedef unsigned int u32;

// scratch (BSS zero covers first call; kernels self-reset for graph replay)
__device__ int    g_cnt[NPAIR<<CSH];
__device__ u64    g_cand[NPAIR*CAP];        // (flip(logit)<<32) | (0x7FFFFFFF - n)
__device__ float  g_cls_scores[NPAIR*KMAX];
__device__ float  g_cls_boxes[NPAIR*KMAX*4];
__device__ float2 g_dims2[45];              // fp64-exact anchor dims (written by scan block 0)
__device__ int    g_img_arrive[BATCH];      // per-image arrival counters

__device__ __forceinline__ float sigmoidf_(float x){ return 1.0f/(1.0f+expf(-x)); }
__device__ __forceinline__ u32 flip_f(u32 u){ return (u & 0x80000000u) ? ~u : (u | 0x80000000u); }
__device__ __forceinline__ float unflip_f(u32 u){
    return __uint_as_float((u & 0x80000000u) ? (u ^ 0x80000000u) : ~u);
}

// ================= sweep: flat float4 grid-stride, ILP=8, streaming loads =================
__device__ __forceinline__ void scan_one(float4 v, int e){
    float m = fmaxf(fmaxf(v.x,v.y), fmaxf(v.z,v.w));
    if (m > FLOOR_LOGIT){
        int row = e/21, chunk = e - row*21;
        if (chunk){                                   // chunk 0 = box quad, skip
            int b = row/NANCH, n = row - b*NANCH;
            int pb = b*NC + (chunk-1)*4;
            float vv[4] = {v.x, v.y, v.z, v.w};
            #pragma unroll
            for (int q = 0; q < 4; q++){
                if (vv[q] > FLOOR_LOGIT){
                    int p = pb + q;
                    int slot = atomicAdd(&g_cnt[p<<CSH], 1);
                    if (slot < CAP)
                        g_cand[p*CAP + slot] =
                            ((u64)(__float_as_uint(vv[q]) | 0x80000000u) << 32) | (u32)(0x7FFFFFFF - n);
                }
            }
        }
    }
}

__global__ __launch_bounds__(256) void k_scan(const float4* __restrict__ pred4){
    // block 0: compute the 45 fp64-exact anchor dims ONCE for the whole grid
    if (blockIdx.x == 0 && threadIdx.x < 45){
        int t = threadIdx.x;
        int lvl = t/9, k = t%9, ri = k/3, si = k%3;
        double side = 32.0 * (double)(1 << lvl);
        double area = side*side;
        double ratio = (ri==0) ? 0.5 : ((ri==1) ? 1.0 : 2.0);
        double scale = (si==0) ? 1.0 : ((si==1) ? 1.2599210498948732 : 1.5874010519681994);
        double ah = sqrt(area / ratio);
        double aw = area / ah;
        g_dims2[t] = make_float2((float)(scale*aw), (float)(scale*ah));
    }

    const int TOT = NROWS*21;                 // 12,889,800 float4s
    const int S = gridDim.x*blockDim.x;
    int e = blockIdx.x*blockDim.x + threadIdx.x;
    for (; e + 7*S < TOT; e += 8*S){
        float4 v0 = __ldcs(pred4 + e);
        float4 v1 = __ldcs(pred4 + e + S);
        float4 v2 = __ldcs(pred4 + e + 2*S);
        float4 v3 = __ldcs(pred4 + e + 3*S);
        float4 v4 = __ldcs(pred4 + e + 4*S);
        float4 v5 = __ldcs(pred4 + e + 5*S);
        float4 v6 = __ldcs(pred4 + e + 6*S);
        float4 v7 = __ldcs(pred4 + e + 7*S);
        float m0 = fmaxf(fmaxf(v0.x,v0.y), fmaxf(v0.z,v0.w));
        float m1 = fmaxf(fmaxf(v1.x,v1.y), fmaxf(v1.z,v1.w));
        float m2 = fmaxf(fmaxf(v2.x,v2.y), fmaxf(v2.z,v2.w));
        float m3 = fmaxf(fmaxf(v3.x,v3.y), fmaxf(v3.z,v3.w));
        float m4 = fmaxf(fmaxf(v4.x,v4.y), fmaxf(v4.z,v4.w));
        float m5 = fmaxf(fmaxf(v5.x,v5.y), fmaxf(v5.z,v5.w));
        float m6 = fmaxf(fmaxf(v6.x,v6.y), fmaxf(v6.z,v6.w));
        float m7 = fmaxf(fmaxf(v7.x,v7.y), fmaxf(v7.z,v7.w));
        float mm = fmaxf(fmaxf(fmaxf(m0,m1), fmaxf(m2,m3)),
                         fmaxf(fmaxf(m4,m5), fmaxf(m6,m7)));
        if (mm > FLOOR_LOGIT){
            scan_one(v0, e);        scan_one(v1, e + S);
            scan_one(v2, e + 2*S);  scan_one(v3, e + 3*S);
            scan_one(v4, e + 4*S);  scan_one(v5, e + 5*S);
            scan_one(v6, e + 6*S);  scan_one(v7, e + 7*S);
        }
    }
    for (; e < TOT; e += S) scan_one(__ldcs(pred4 + e), e);
}

// ================= warp-aggregated histogram add (uniform warps only) =================
__device__ __forceinline__ void hist_add(int* bins, int digit, bool act){
    int lane = threadIdx.x & 31;
    int v = act ? digit : (512 + lane);               // distinct sentinels for inactive lanes
    unsigned m = __match_any_sync(0xFFFFFFFFu, v);
    if (act && ((m & ((1u<<lane)-1u)) == 0))
        atomicAdd(&bins[digit], __popc(m));
}

__device__ __forceinline__ void radix_scan_bins(int* bins, u32 prefix, int need,
                                                u32* sh_pref, int* sh_need, int* sh_tc){
    int tid = threadIdx.x;
    if (tid < 32){
        int c[8]; int lsum = 0;
        #pragma unroll
        for (int j = 0; j < 8; j++){ c[j] = bins[(tid<<3)+j]; lsum += c[j]; }
        int acc = lsum;
        #pragma unroll
        for (int off = 1; off < 32; off <<= 1){
            int t2 = __shfl_down_sync(0xFFFFFFFFu, acc, off);
            if (tid + off < 32) acc += t2;
        }
        int cum = acc - lsum;      // count with higher digit
        #pragma unroll
        for (int j = 7; j >= 0; j--){
            int nx = cum + c[j];
            if (cum < need && need <= nx){
                *sh_pref = (prefix << 8) | (u32)((tid<<3) + j);
                *sh_need = need - cum;
                *sh_tc   = c[j];
            }
            cum = nx;
        }
    }
}

// 32-bit radix select over register-resident keys (uniform NK loop)
template<int NK>
__device__ u32 radix_select32(const u64* key, bool lo_mode, u32 hi_match, int T,
                              int* bins, u32* sh_pref, int* sh_need, int* sh_tc,
                              int* ret_need, int* ret_tc){
    u32 prefix = 0; int need = T, tc = 0;
    for (int pass = 0; pass < 4; pass++){
        const int shift = 24 - (pass<<3);
        for (int i = threadIdx.x; i < 256; i += blockDim.x) bins[i] = 0;
        __syncthreads();
        #pragma unroll
        for (int q = 0; q < NK; q++){
            u64 k = key[q];
            u32 hi = (u32)(k >> 32);
            u32 f  = lo_mode ? (u32)k : hi;
            bool ok = (k != 0ull) && (!lo_mode || hi == hi_match) &&
                      (pass == 0 || (f >> (shift+8)) == prefix);
            hist_add(bins, (int)((f >> shift) & 255), ok);
        }
        __syncthreads();
        radix_scan_bins(bins, prefix, need, sh_pref, sh_need, sh_tc);
        __syncthreads();
        prefix = *sh_pref; need = *sh_need; tc = *sh_tc;
        __syncthreads();
    }
    *ret_need = need; *ret_tc = tc;
    return prefix;
}

template<int NK>
__device__ u64 topk_thr(const u64* key, int T, int* bins, u32* shp, int* shn, int* sht){
    int need2, tc;
    u32 thr_hi = radix_select32<NK>(key, false, 0, T, bins, shp, shn, sht, &need2, &tc);
    u32 thr_lo = 0;
    if (tc != need2){
        int d1, d2;
        thr_lo = radix_select32<NK>(key, true, thr_hi, need2, bins, shp, shn, sht, &d1, &d2);
    }
    return ((u64)thr_hi << 32) | thr_lo;
}

// 32-bit radix select over per-image scores read from global (register-light, uniform trips)
__device__ u32 merge_select(const float* __restrict__ cs, bool lo_mode, u32 hi_match, int T,
                            int* bins, u32* sh_pref, int* sh_need, int* sh_tc,
                            int* ret_need, int* ret_tc){
    const int M = NC*KMAX;
    const int NIT = (M + 255)/256;            // 32, uniform
    u32 prefix = 0; int need = T, tc = 0;
    for (int pass = 0; pass < 4; pass++){
        const int shift = 24 - (pass<<3);
        for (int i = threadIdx.x; i < 256; i += blockDim.x) bins[i] = 0;
        __syncthreads();
        for (int it = 0; it < NIT; it++){
            int s = threadIdx.x + (it<<8);
            bool in = (s < M);
            float sc = in ? cs[s] : 0.0f;
            u32 hi = flip_f(__float_as_uint(sc));
            u32 lo = (u32)(0x7FFFFFFF - s);
            u32 f  = lo_mode ? lo : hi;
            bool ok = in && (!lo_mode || hi == hi_match) &&
                      (pass == 0 || (f >> (shift+8)) == prefix);
            hist_add(bins, (int)((f >> shift) & 255), ok);
        }
        __syncthreads();
        radix_scan_bins(bins, prefix, need, sh_pref, sh_need, sh_tc);
        __syncthreads();
        prefix = *sh_pref; need = *sh_need; tc = *sh_tc;
        __syncthreads();
    }
    *ret_need = need; *ret_tc = tc;
    return prefix;
}

// ================= per (image,class): top-100 + greedy NMS; last block per image merges =================
__global__ __launch_bounds__(256) void k_classnms(const float* __restrict__ pred,
                                                  float* __restrict__ out){
    const int p = blockIdx.x;
    const int tid = threadIdx.x;
    const int bimg = p / NC;

    __shared__ int bins[256];
    __shared__ u32 sh_pref; __shared__ int sh_need, sh_tc, s_n, s_cnt, s_rank, s_valid;
    __shared__ u64 s_key[112];
    __shared__ u64 s_sorted[KMAX];
    __shared__ float ssc[KMAX], sb0[KMAX], sb1[KMAX], sb2[KMAX], sb3[KMAX];
    __shared__ u64 sup0[KMAX], sup1[KMAX], s_keep0, s_keep1;

    int cnt = g_cnt[p<<CSH];

    // exact fallback (block-uniform branch; never taken on this data, guards any data)
    if (cnt < KMAX || cnt > CAP){
        const int c = p % NC;
        const float* base = pred + (size_t)bimg*NANCH*NF + 4 + c;
        if (tid == 0) s_cnt = 0;
        __syncthreads();
        int loc = 0;
        for (int n = tid; n < NANCH; n += 256)
            if (sigmoidf_(base[(size_t)n*NF]) > SCORE_TH) loc++;
        atomicAdd(&s_cnt, loc);
        __syncthreads();
        int total = s_cnt;
        int T0 = min(total, KMAX);
        if (T0 == 0) cnt = 0;
        else {
            u64 lo = 0ull, hi = ~0ull;
            while (lo < hi){
                u64 mid = lo + ((hi - lo) >> 1) + 1ull;
                __syncthreads();
                if (tid == 0) s_cnt = 0;
                __syncthreads();
                int cc = 0;
                for (int n = tid; n < NANCH; n += 256){
                    float v = base[(size_t)n*NF];
                    if (sigmoidf_(v) > SCORE_TH){
                        u64 kk = ((u64)flip_f(__float_as_uint(v)) << 32) | (u32)(0x7FFFFFFF - n);
                        if (kk >= mid) cc++;
                    }
                }
                atomicAdd(&s_cnt, cc);
                __syncthreads();
                if (s_cnt >= T0) lo = mid; else hi = mid - 1;
            }
            __syncthreads();
            if (tid == 0) s_cnt = 0;
            __syncthreads();
            for (int n = tid; n < NANCH; n += 256){
                float v = base[(size_t)n*NF];
                if (sigmoidf_(v) > SCORE_TH){
                    u64 kk = ((u64)flip_f(__float_as_uint(v)) << 32) | (u32)(0x7FFFFFFF - n);
                    if (kk >= lo){
                        int sl = atomicAdd(&s_cnt, 1);
                        if (sl < CAP) g_cand[p*CAP + sl] = kk;
                    }
                }
            }
            cnt = T0;
        }
        __syncthreads();
    }

    const int T = min(cnt, KMAX);
    u64 key[4];
    #pragma unroll
    for (int q = 0; q < 4; q++){
        int s = tid + (q<<8);
        key[q] = (s < cnt) ? g_cand[p*CAP + s] : 0ull;
    }

    if (tid == 0) s_n = 0;
    if (tid < KMAX){ ssc[tid] = -1.0f; sb0[tid]=0.f; sb1[tid]=0.f; sb2[tid]=0.f; sb3[tid]=0.f;
                     sup0[tid] = 0ull; sup1[tid] = 0ull; }
    __syncthreads();

    u64 thr = 1ull;                              // cnt<=KMAX: take all nonzero keys
    if (cnt > KMAX) thr = topk_thr<4>(key, T, bins, &sh_pref, &sh_need, &sh_tc);

    #pragma unroll
    for (int q = 0; q < 4; q++){
        u64 k = key[q];
        if (k && k >= thr){
            int pos = atomicAdd(&s_n, 1);
            if (pos < 112) s_key[pos] = k;
        }
    }
    __syncthreads();
    const int mG = min(s_n, 112);

    if (tid < mG){
        u64 k = s_key[tid];
        int rank = 0;
        #pragma unroll 4
        for (int jj = 0; jj < mG; jj++) rank += (s_key[jj] > k);
        if (rank < T){
            float logit = unflip_f((u32)(k >> 32));
            float sc = sigmoidf_(logit);
            int n = 0x7FFFFFFF - (int)(u32)(k & 0xFFFFFFFFull);
            int lvl = (n>=57600) + (n>=72000) + (n>=75600) + (n>=76500);
            int off = (lvl==0)?0 : (lvl==1)?57600 : (lvl==2)?72000 : (lvl==3)?75600 : 76500;
            int local = n - off;
            int k9   = local % 9;
            int cell = local / 9;
            int sh = 4 - lvl;
            int iy = (cell/5) >> sh;
            int jx = cell - iy*(5<<sh);
            float stridef = (float)(8<<lvl);
            float2 d = g_dims2[lvl*9 + k9];
            float4 bp = __ldg((const float4*)pred + (size_t)(bimg*NANCH + n)*21);
            float cx = ((float)jx + 0.5f)*stridef;
            float cy = ((float)iy + 0.5f)*stridef;
            float x  = (bp.x*0.1f)*d.x + cx;
            float y  = (bp.y*0.1f)*d.y + cy;
            float ww = expf(bp.z*0.2f)*d.x;
            float hh = expf(bp.w*0.2f)*d.y;
            ssc[rank] = sc;
            sb0[rank] = x - ww*0.5f; sb1[rank] = y - hh*0.5f;
            sb2[rank] = x + ww*0.5f; sb3[rank] = y + hh*0.5f;
        }
    }
    __syncthreads();

    // flattened pair-parallel suppression masks: pair q -> (i,j), i<j
    const int P = T*(T-1)/2;
    for (int q = tid; q < P; q += 256){
        float qf = (float)q;
        int j = (int)((1.0f + sqrtf(1.0f + 8.0f*qf))*0.5f);
        while (j*(j-1)/2 > q) j--;
        while (j*(j+1)/2 <= q) j++;
        int i = q - j*(j-1)/2;
        float ax=sb0[i], ay=sb1[i], az=sb2[i], aw=sb3[i];
        float bx=sb0[j], by=sb1[j], bz=sb2[j], bw=sb3[j];
        float ltx = fmaxf(ax,bx), lty = fmaxf(ay,by);
        float rbx = fminf(az,bz), rby = fminf(aw,bw);
        float w = fmaxf(rbx-ltx, 0.0f), h = fmaxf(rby-lty, 0.0f);
        float inter = w*h;
        float a1 = (az-ax)*(aw-ay);
        float a2 = (bz-bx)*(bw-by);
        float iou = inter / (a1 + a2 - inter + 1e-8f);
        if (iou > IOU_THR)
            atomicOr((j < 64) ? &sup0[i] : &sup1[i], 1ull << (j & 63));
    }
    __syncthreads();

    if (tid == 0){
        u64 k0, k1;
        if (T >= 64){ k0 = ~0ull; k1 = (T == 64) ? 0ull : ((1ull << (T-64)) - 1ull); }
        else        { k0 = (T == 0) ? 0ull : ((1ull << T) - 1ull); k1 = 0ull; }
        for (int i = 0; i < T; i++){
            bool kept = (i < 64) ? ((k0 >> i) & 1ull) : ((k1 >> (i-64)) & 1ull);
            if (kept){ k0 &= ~sup0[i]; k1 &= ~sup1[i]; }
        }
        s_keep0 = k0; s_keep1 = k1;
        g_cnt[p<<CSH] = 0;    // re-arm for next launch/replay
    }
    __syncthreads();
    if (tid < KMAX){
        bool kept = (tid < T) && ((tid < 64) ? ((s_keep0 >> tid) & 1ull) : ((s_keep1 >> (tid-64)) & 1ull));
        g_cls_scores[p*KMAX + tid] = kept ? ssc[tid] : -1.0f;
        ((float4*)g_cls_boxes)[p*KMAX + tid] = make_float4(sb0[tid], sb1[tid], sb2[tid], sb3[tid]);
    }

    // ---------- arrival; last block of the image performs the merge ----------
    __threadfence();
    if (tid == 0) s_rank = atomicAdd(&g_img_arrive[bimg], 1);
    __syncthreads();
    if (s_rank != NC-1) return;

    if (tid == 0) g_img_arrive[bimg] = 0;     // re-arm for replay
    __threadfence();

    const int M = NC*KMAX;
    const float* cs = g_cls_scores + bimg*M;
    const int NIT = (M + 255)/256;            // 32, uniform

    int need2, tc;
    u32 thr_hi = merge_select(cs, false, 0, KMAX, bins, &sh_pref, &sh_need, &sh_tc, &need2, &tc);
    u32 thr_lo = 0;
    if (tc != need2){
        int d1, d2;
        thr_lo = merge_select(cs, true, thr_hi, need2, bins, &sh_pref, &sh_need, &sh_tc, &d1, &d2);
    }
    u64 mthr = ((u64)thr_hi << 32) | thr_lo;

    if (tid == 0){ s_n = 0; s_valid = 0; }
    __syncthreads();
    for (int it = 0; it < NIT; it++){
        int s = tid + (it<<8);
        if (s < M){
            float sc = cs[s];
            u64 kk = ((u64)flip_f(__float_as_uint(sc)) << 32) | (u32)(0x7FFFFFFF - s);
            if (kk >= mthr){
                int pos = atomicAdd(&s_n, 1);
                if (pos < 112) s_key[pos] = kk;
            }
        }
    }
    __syncthreads();
    const int mGm = min(s_n, 112);

    if (tid < mGm){
        u64 k = s_key[tid];
        int rank = 0;
        #pragma unroll 4
        for (int jj = 0; jj < mGm; jj++) rank += (s_key[jj] > k);
        if (rank < KMAX) s_sorted[rank] = k;
    }
    __syncthreads();

    if (tid < KMAX){
        u64 k = s_sorted[tid];
        float sc = unflip_f((u32)(k >> 32));
        int s = 0x7FFFFFFF - (int)(u32)(k & 0xFFFFFFFFull);
        bool good = sc > 0.0f;
        float4 bx = make_float4(0,0,0,0); float clsf = 0.0f;
        if (good){
            bx = ((const float4*)g_cls_boxes)[bimg*M + s];
            clsf = (float)(s / KMAX);
            atomicAdd(&s_valid, 1);
        }
        ((float4*)out)[bimg*KMAX + tid] = bx;                       // boxes  [0, 3200)
        out[BATCH*KMAX*4 + bimg*KMAX + tid] = fmaxf(sc, 0.0f);      // scores [3200, 4000)
        out[BATCH*KMAX*5 + bimg*KMAX + tid] = clsf;                 // classes[4000, 4800)
    }
    __syncthreads();
    if (tid == 0) out[BATCH*KMAX*6 + bimg] = (float)s_valid;        // valid  [4800, 4808)
}

extern "C" void kernel_launch(void* const* d_in, const int* in_sizes, int n_in,
                              void* d_out, int out_size){
    const float* pred = nullptr;
    const int PRED_SZ = BATCH*NANCH*NF;
    int best = -1;
    for (int i = 0; i < n_in; i++){
        if (in_sizes[i] == PRED_SZ){ pred = (const float*)d_in[i]; break; }
        if (best < 0 || in_sizes[i] > in_sizes[best]) best = i;
    }
    if (!pred) pred = (const float*)d_in[best < 0 ? 0 : best];

    float* out = (float*)d_out;
    (void)out_size;

    k_scan<<<2048, 256>>>((const float4*)pred);
    k_classnms<<<NPAIR, 256>>>(pred, out);
}

// round 8
// speedup vs baseline: 1.7539x; 1.7539x over previous
#include <cuda_runtime.h>
#include <stdint.h>
#include <math.h>

#define BATCH   8
#define NANCH   76725
#define NROWS   (BATCH*NANCH)
#define NC      80
#define NF      84
#define KMAX    100
#define CAP     1024
#define NPAIR   (BATCH*NC)
#define FLOOR_LOGIT 2.5f
#define SCORE_TH 0.05f
#define IOU_THR 0.5f
#define CSH     5

typedef unsigned long long u64;
typedef unsigned int u32;

// scratch (BSS zero covers first call; classnms re-zeros g_cnt each launch)
__device__ int   g_cnt[NPAIR<<CSH];
__device__ u64   g_cand[NPAIR*CAP];        // (flip(logit)<<32) | (0x7FFFFFFF - n)
__device__ float g_cls_scores[NPAIR*KMAX];
__device__ float g_cls_boxes[NPAIR*KMAX*4];

__device__ __forceinline__ float sigmoidf_(float x){ return 1.0f/(1.0f+expf(-x)); }
__device__ __forceinline__ u32 flip_f(u32 u){ return (u & 0x80000000u) ? ~u : (u | 0x80000000u); }
__device__ __forceinline__ float unflip_f(u32 u){
    return __uint_as_float((u & 0x80000000u) ? (u ^ 0x80000000u) : ~u);
}

// ================= sweep: flat float4 grid-stride, ILP=8 =================
__device__ __forceinline__ void scan_one(float4 v, int e){
    float m = fmaxf(fmaxf(v.x,v.y), fmaxf(v.z,v.w));
    if (m > FLOOR_LOGIT){
        int row = e/21, chunk = e - row*21;
        if (chunk){                                   // chunk 0 = box quad, skip
            int b = row/NANCH, n = row - b*NANCH;
            int pb = b*NC + (chunk-1)*4;
            float vv[4] = {v.x, v.y, v.z, v.w};
            #pragma unroll
            for (int q = 0; q < 4; q++){
                if (vv[q] > FLOOR_LOGIT){
                    int p = pb + q;
                    int slot = atomicAdd(&g_cnt[p<<CSH], 1);
                    if (slot < CAP)
                        g_cand[p*CAP + slot] =
                            ((u64)(__float_as_uint(vv[q]) | 0x80000000u) << 32) | (u32)(0x7FFFFFFF - n);
                }
            }
        }
    }
}

__global__ __launch_bounds__(256) void k_scan(const float4* __restrict__ pred4){
    const int TOT = NROWS*21;                 // 12,889,800 float4s
    const int S = gridDim.x*blockDim.x;
    int e = blockIdx.x*blockDim.x + threadIdx.x;
    for (; e + 7*S < TOT; e += 8*S){
        float4 v0 = __ldg(pred4 + e);
        float4 v1 = __ldg(pred4 + e + S);
        float4 v2 = __ldg(pred4 + e + 2*S);
        float4 v3 = __ldg(pred4 + e + 3*S);
        float4 v4 = __ldg(pred4 + e + 4*S);
        float4 v5 = __ldg(pred4 + e + 5*S);
        float4 v6 = __ldg(pred4 + e + 6*S);
        float4 v7 = __ldg(pred4 + e + 7*S);
        float m0 = fmaxf(fmaxf(v0.x,v0.y), fmaxf(v0.z,v0.w));
        float m1 = fmaxf(fmaxf(v1.x,v1.y), fmaxf(v1.z,v1.w));
        float m2 = fmaxf(fmaxf(v2.x,v2.y), fmaxf(v2.z,v2.w));
        float m3 = fmaxf(fmaxf(v3.x,v3.y), fmaxf(v3.z,v3.w));
        float m4 = fmaxf(fmaxf(v4.x,v4.y), fmaxf(v4.z,v4.w));
        float m5 = fmaxf(fmaxf(v5.x,v5.y), fmaxf(v5.z,v5.w));
        float m6 = fmaxf(fmaxf(v6.x,v6.y), fmaxf(v6.z,v6.w));
        float m7 = fmaxf(fmaxf(v7.x,v7.y), fmaxf(v7.z,v7.w));
        float mm = fmaxf(fmaxf(fmaxf(m0,m1), fmaxf(m2,m3)),
                         fmaxf(fmaxf(m4,m5), fmaxf(m6,m7)));
        if (mm > FLOOR_LOGIT){
            scan_one(v0, e);        scan_one(v1, e + S);
            scan_one(v2, e + 2*S);  scan_one(v3, e + 3*S);
            scan_one(v4, e + 4*S);  scan_one(v5, e + 5*S);
            scan_one(v6, e + 6*S);  scan_one(v7, e + 7*S);
        }
    }
    for (; e < TOT; e += S) scan_one(__ldg(pred4 + e), e);
}

// ================= exact radix-select machinery (direct atomics, tie-aware) =================
__device__ __forceinline__ void radix_scan_bins(int* bins, u32 prefix, int need,
                                                u32* sh_pref, int* sh_need, int* sh_tc){
    int tid = threadIdx.x;
    if (tid < 32){
        int c[8]; int lsum = 0;
        #pragma unroll
        for (int j = 0; j < 8; j++){ c[j] = bins[(tid<<3)+j]; lsum += c[j]; }
        int acc = lsum;
        #pragma unroll
        for (int off = 1; off < 32; off <<= 1){
            int t2 = __shfl_down_sync(0xFFFFFFFFu, acc, off);
            if (tid + off < 32) acc += t2;
        }
        int cum = acc - lsum;      // count with higher digit
        #pragma unroll
        for (int j = 7; j >= 0; j--){
            int nx = cum + c[j];
            if (cum < need && need <= nx){
                *sh_pref = (prefix << 8) | (u32)((tid<<3) + j);
                *sh_need = need - cum;
                *sh_tc   = c[j];
            }
            cum = nx;
        }
    }
}

// 32-bit radix select over register-resident keys.
// act_pos: restrict to keys whose hi top bit is set (positive scores).
template<int NK>
__device__ u32 radix_select32(const u64* key, bool lo_mode, u32 hi_match, bool act_pos, int T,
                              int* bins, u32* sh_pref, int* sh_need, int* sh_tc,
                              int* ret_need, int* ret_tc){
    u32 prefix = 0; int need = T, tc = 0;
    for (int pass = 0; pass < 4; pass++){
        const int shift = 24 - (pass<<3);
        for (int i = threadIdx.x; i < 256; i += blockDim.x) bins[i] = 0;
        __syncthreads();
        #pragma unroll
        for (int q = 0; q < NK; q++){
            u64 k = key[q];
            if (k){
                u32 hi = (u32)(k >> 32);
                u32 f  = lo_mode ? (u32)k : hi;
                bool ok = (!act_pos || (hi & 0x80000000u)) &&
                          (!lo_mode || hi == hi_match) &&
                          (pass == 0 || (f >> (shift+8)) == prefix);
                if (ok) atomicAdd(&bins[(f >> shift) & 255], 1);
            }
        }
        __syncthreads();
        radix_scan_bins(bins, prefix, need, sh_pref, sh_need, sh_tc);
        __syncthreads();
        prefix = *sh_pref; need = *sh_need; tc = *sh_tc;
        __syncthreads();
    }
    *ret_need = need; *ret_tc = tc;
    return prefix;
}

template<int NK>
__device__ u64 topk_thr(const u64* key, bool act_pos, int T,
                        int* bins, u32* shp, int* shn, int* sht){
    int need2, tc;
    u32 thr_hi = radix_select32<NK>(key, false, 0, act_pos, T, bins, shp, shn, sht, &need2, &tc);
    u32 thr_lo = 0;
    if (tc != need2){
        int d1, d2;
        thr_lo = radix_select32<NK>(key, true, thr_hi, act_pos, need2, bins, shp, shn, sht, &d1, &d2);
    }
    return ((u64)thr_hi << 32) | thr_lo;
}

// pair index q -> (i,j), i<j
__device__ __forceinline__ void pair_ij(int q, int* pi, int* pj){
    float qf = (float)q;
    int j = (int)((1.0f + sqrtf(1.0f + 8.0f*qf))*0.5f);
    while (j*(j-1)/2 > q) j--;
    while (j*(j+1)/2 <= q) j++;
    *pi = q - j*(j-1)/2;
    *pj = j;
}

// ================= per (image,class): top-100 + greedy NMS (512 threads) =================
__global__ __launch_bounds__(512) void k_classnms(const float* __restrict__ pred){
    const int p = blockIdx.x;
    const int tid = threadIdx.x;
    const int bimg = p / NC;

    __shared__ float2 s_dims[45];
    __shared__ int bins[256];
    __shared__ u32 sh_pref; __shared__ int sh_need, sh_tc, s_n, s_cnt;
    __shared__ u64 s_key[112];
    __shared__ int s_rankc[112];
    __shared__ float ssc[KMAX], sb0[KMAX], sb1[KMAX], sb2[KMAX], sb3[KMAX];
    __shared__ u32 supw[KMAX*4];
    __shared__ u32 s_keep[4];

    if (tid < 45){     // fp64-exact anchor dims (45 lanes once per block; measured OK)
        int lvl = tid/9, k = tid%9, ri = k/3, si = k%3;
        double side = 32.0 * (double)(1 << lvl);
        double area = side*side;
        double ratio = (ri==0) ? 0.5 : ((ri==1) ? 1.0 : 2.0);
        double scale = (si==0) ? 1.0 : ((si==1) ? 1.2599210498948732 : 1.5874010519681994);
        double ah = sqrt(area / ratio);
        double aw = area / ah;
        s_dims[tid] = make_float2((float)(scale*aw), (float)(scale*ah));
    }

    int cnt = g_cnt[p<<CSH];

    // exact fallback (block-uniform; never taken on this data, guards any data)
    if (cnt < KMAX || cnt > CAP){
        const int c = p % NC;
        const float* base = pred + (size_t)bimg*NANCH*NF + 4 + c;
        if (tid == 0) s_cnt = 0;
        __syncthreads();
        int loc = 0;
        for (int n = tid; n < NANCH; n += 512)
            if (sigmoidf_(base[(size_t)n*NF]) > SCORE_TH) loc++;
        atomicAdd(&s_cnt, loc);
        __syncthreads();
        int total = s_cnt;
        int T0 = min(total, KMAX);
        if (T0 == 0) cnt = 0;
        else {
            u64 lo = 0ull, hi = ~0ull;
            while (lo < hi){
                u64 mid = lo + ((hi - lo) >> 1) + 1ull;
                __syncthreads();
                if (tid == 0) s_cnt = 0;
                __syncthreads();
                int cc = 0;
                for (int n = tid; n < NANCH; n += 512){
                    float v = base[(size_t)n*NF];
                    if (sigmoidf_(v) > SCORE_TH){
                        u64 kk = ((u64)flip_f(__float_as_uint(v)) << 32) | (u32)(0x7FFFFFFF - n);
                        if (kk >= mid) cc++;
                    }
                }
                atomicAdd(&s_cnt, cc);
                __syncthreads();
                if (s_cnt >= T0) lo = mid; else hi = mid - 1;
            }
            __syncthreads();
            if (tid == 0) s_cnt = 0;
            __syncthreads();
            for (int n = tid; n < NANCH; n += 512){
                float v = base[(size_t)n*NF];
                if (sigmoidf_(v) > SCORE_TH){
                    u64 kk = ((u64)flip_f(__float_as_uint(v)) << 32) | (u32)(0x7FFFFFFF - n);
                    if (kk >= lo){
                        int sl = atomicAdd(&s_cnt, 1);
                        if (sl < CAP) g_cand[p*CAP + sl] = kk;
                    }
                }
            }
            cnt = T0;
        }
        __syncthreads();
    }

    const int T = min(cnt, KMAX);
    u64 key[2];
    #pragma unroll
    for (int q = 0; q < 2; q++){
        int s = tid + (q<<9);
        key[q] = (s < cnt) ? g_cand[p*CAP + s] : 0ull;
    }

    if (tid == 0) s_n = 0;
    if (tid < KMAX){ ssc[tid] = -1.0f; sb0[tid]=0.f; sb1[tid]=0.f; sb2[tid]=0.f; sb3[tid]=0.f; }
    if (tid < 112) s_rankc[tid] = 0;
    if (tid < KMAX*4) supw[tid] = 0u;
    __syncthreads();

    u64 thr = 1ull;                              // cnt<=KMAX: take all nonzero keys
    if (cnt > KMAX) thr = topk_thr<2>(key, false, T, bins, &sh_pref, &sh_need, &sh_tc);

    #pragma unroll
    for (int q = 0; q < 2; q++){
        u64 k = key[q];
        if (k && k >= thr){
            int pos = atomicAdd(&s_n, 1);
            if (pos < 112) s_key[pos] = k;
        }
    }
    __syncthreads();
    const int mG = min(s_n, 112);

    // pair-parallel rank counting (keys distinct): rank = #{greater}
    const int PR = mG*(mG-1)/2;
    for (int q = tid; q < PR; q += 512){
        int i, j; pair_ij(q, &i, &j);
        if (s_key[i] < s_key[j]) atomicAdd(&s_rankc[i], 1);
        else                     atomicAdd(&s_rankc[j], 1);
    }
    __syncthreads();

    if (tid < mG){
        int rank = s_rankc[tid];
        if (rank < T){
            u64 k = s_key[tid];
            float logit = unflip_f((u32)(k >> 32));
            float sc = sigmoidf_(logit);
            int n = 0x7FFFFFFF - (int)(u32)(k & 0xFFFFFFFFull);
            int lvl = (n>=57600) + (n>=72000) + (n>=75600) + (n>=76500);
            int off = (lvl==0)?0 : (lvl==1)?57600 : (lvl==2)?72000 : (lvl==3)?75600 : 76500;
            int local = n - off;
            int k9   = local % 9;
            int cell = local / 9;
            int sh = 4 - lvl;
            int iy = (cell/5) >> sh;
            int jx = cell - iy*(5<<sh);
            float stridef = (float)(8<<lvl);
            float2 d = s_dims[lvl*9 + k9];
            float4 bp = __ldg((const float4*)pred + (size_t)(bimg*NANCH + n)*21);
            float cx = ((float)jx + 0.5f)*stridef;
            float cy = ((float)iy + 0.5f)*stridef;
            float x  = (bp.x*0.1f)*d.x + cx;
            float y  = (bp.y*0.1f)*d.y + cy;
            float ww = expf(bp.z*0.2f)*d.x;
            float hh = expf(bp.w*0.2f)*d.y;
            ssc[rank] = sc;
            sb0[rank] = x - ww*0.5f; sb1[rank] = y - hh*0.5f;
            sb2[rank] = x + ww*0.5f; sb3[rank] = y + hh*0.5f;
        }
    }
    __syncthreads();

    // pair-parallel suppression masks (32-bit atomicOr, native ATOMS)
    const int P = T*(T-1)/2;
    for (int q = tid; q < P; q += 512){
        int i, j; pair_ij(q, &i, &j);
        float ax=sb0[i], ay=sb1[i], az=sb2[i], aw=sb3[i];
        float bx=sb0[j], by=sb1[j], bz=sb2[j], bw=sb3[j];
        float ltx = fmaxf(ax,bx), lty = fmaxf(ay,by);
        float rbx = fminf(az,bz), rby = fminf(aw,bw);
        float w = fmaxf(rbx-ltx, 0.0f), h = fmaxf(rby-lty, 0.0f);
        float inter = w*h;
        float a1 = (az-ax)*(aw-ay);
        float a2 = (bz-bx)*(bw-by);
        float iou = inter / (a1 + a2 - inter + 1e-8f);
        if (iou > IOU_THR)
            atomicOr(&supw[i*4 + (j>>5)], 1u << (j & 31));
    }
    __syncthreads();

    // sequential greedy on 4x u32 masks (exact reference semantics)
    if (tid == 0){
        u32 keep[4];
        #pragma unroll
        for (int w = 0; w < 4; w++){
            int rem = T - w*32;
            keep[w] = (rem >= 32) ? 0xFFFFFFFFu : (rem <= 0 ? 0u : ((1u<<rem)-1u));
        }
        for (int i = 0; i < T; i++){
            if (keep[i>>5] & (1u << (i&31))){
                keep[0] &= ~supw[i*4+0]; keep[1] &= ~supw[i*4+1];
                keep[2] &= ~supw[i*4+2]; keep[3] &= ~supw[i*4+3];
            }
        }
        s_keep[0]=keep[0]; s_keep[1]=keep[1]; s_keep[2]=keep[2]; s_keep[3]=keep[3];
        g_cnt[p<<CSH] = 0;    // re-arm for next launch/replay
    }
    __syncthreads();
    if (tid < KMAX){
        bool kept = (tid < T) && (s_keep[tid>>5] & (1u << (tid&31)));
        g_cls_scores[p*KMAX + tid] = kept ? ssc[tid] : -1.0f;
        ((float4*)g_cls_boxes)[p*KMAX + tid] = make_float4(sb0[tid], sb1[tid], sb2[tid], sb3[tid]);
    }
}

// ================= per image merge: top-100 of 8000, write outputs =================
__global__ __launch_bounds__(256) void k_merge(float* __restrict__ out){
    const int b = blockIdx.x;
    const int tid = threadIdx.x;
    const int M = NC*KMAX;   // 8000

    u64 key[32];
    int npos_loc = 0;
    #pragma unroll
    for (int q = 0; q < 32; q++){
        int s = tid + (q<<8);
        u64 kk = 0ull;
        if (s < M){
            float sc = g_cls_scores[b*M + s];
            kk = ((u64)flip_f(__float_as_uint(sc)) << 32) | (u32)(0x7FFFFFFF - s);
            if (sc > 0.0f) npos_loc++;
        }
        key[q] = kk;
    }

    __shared__ int bins[256];
    __shared__ u32 sh_pref; __shared__ int sh_need, sh_tc;
    __shared__ int s_n, s_valid, s_npos;
    __shared__ u64 s_key[112];
    __shared__ int s_rankc[112];
    __shared__ u64 s_sorted[KMAX];

    if (tid == 0){ s_n = 0; s_valid = 0; s_npos = 0; }
    if (tid < 112) s_rankc[tid] = 0;
    __syncthreads();
    // warp-reduced positive count
    for (int o = 16; o; o >>= 1) npos_loc += __shfl_down_sync(0xFFFFFFFFu, npos_loc, o);
    if ((tid & 31) == 0 && npos_loc) atomicAdd(&s_npos, npos_loc);
    __syncthreads();
    const bool pos_only = (s_npos >= KMAX);  // true on real data; rare path stays exact

    u64 thr = topk_thr<32>(key, pos_only, KMAX, bins, &sh_pref, &sh_need, &sh_tc);

    #pragma unroll
    for (int q = 0; q < 32; q++){
        u64 k = key[q];
        bool act = k && (!pos_only || ((u32)(k>>32) & 0x80000000u));
        if (act && k >= thr){
            int pos = atomicAdd(&s_n, 1);
            if (pos < 112) s_key[pos] = k;
        }
    }
    __syncthreads();
    const int mG = min(s_n, 112);

    const int PR = mG*(mG-1)/2;
    for (int q = tid; q < PR; q += 256){
        int i, j; pair_ij(q, &i, &j);
        if (s_key[i] < s_key[j]) atomicAdd(&s_rankc[i], 1);
        else                     atomicAdd(&s_rankc[j], 1);
    }
    __syncthreads();
    if (tid < mG){
        int rank = s_rankc[tid];
        if (rank < KMAX) s_sorted[rank] = s_key[tid];
    }
    __syncthreads();

    if (tid < KMAX){
        u64 k = s_sorted[tid];
        float sc = unflip_f((u32)(k >> 32));
        int s = 0x7FFFFFFF - (int)(u32)(k & 0xFFFFFFFFull);
        bool good = sc > 0.0f;
        float4 bx = make_float4(0,0,0,0); float clsf = 0.0f;
        if (good){
            bx = ((const float4*)g_cls_boxes)[b*M + s];
            clsf = (float)(s / KMAX);
            atomicAdd(&s_valid, 1);
        }
        ((float4*)out)[b*KMAX + tid] = bx;                       // boxes  [0, 3200)
        out[BATCH*KMAX*4 + b*KMAX + tid] = fmaxf(sc, 0.0f);      // scores [3200, 4000)
        out[BATCH*KMAX*5 + b*KMAX + tid] = clsf;                 // classes[4000, 4800)
    }
    __syncthreads();
    if (tid == 0) out[BATCH*KMAX*6 + b] = (float)s_valid;        // valid  [4800, 4808)
}

extern "C" void kernel_launch(void* const* d_in, const int* in_sizes, int n_in,
                              void* d_out, int out_size){
    const float* pred = nullptr;
    const int PRED_SZ = BATCH*NANCH*NF;
    int best = -1;
    for (int i = 0; i < n_in; i++){
        if (in_sizes[i] == PRED_SZ){ pred = (const float*)d_in[i]; break; }
        if (best < 0 || in_sizes[i] > in_sizes[best]) best = i;
    }
    if (!pred) pred = (const float*)d_in[best < 0 ? 0 : best];

    float* out = (float*)d_out;
    (void)out_size;

    k_scan<<<2048, 256>>>((const float4*)pred);
    k_classnms<<<NPAIR, 512>>>(pred);
    k_merge<<<BATCH, 256>>>(out);
}

// round 9
// speedup vs baseline: 2.0206x; 1.1521x over previous
#include <cuda_runtime.h>
#include <stdint.h>
#include <math.h>

#define BATCH   8
#define NANCH   76725
#define NROWS   (BATCH*NANCH)
#define NC      80
#define NF      84
#define KMAX    100
#define CAP     512
#define NPAIR   (BATCH*NC)
#define FLOOR_LOGIT 2.8f
#define SCORE_TH 0.05f
#define IOU_THR 0.5f
#define CSH     5

typedef unsigned long long u64;
typedef unsigned int u32;

// scratch (BSS zero covers first call; classnms re-zeros g_cnt each launch)
__device__ int   g_cnt[NPAIR<<CSH];
__device__ u64   g_cand[NPAIR*CAP];        // (flip(logit)<<32) | (0x7FFFFFFF - n)
__device__ float g_cls_scores[NPAIR*KMAX];
__device__ float g_cls_boxes[NPAIR*KMAX*4];

__device__ __forceinline__ float sigmoidf_(float x){ return 1.0f/(1.0f+expf(-x)); }
__device__ __forceinline__ u32 flip_f(u32 u){ return (u & 0x80000000u) ? ~u : (u | 0x80000000u); }
__device__ __forceinline__ float unflip_f(u32 u){
    return __uint_as_float((u & 0x80000000u) ? (u ^ 0x80000000u) : ~u);
}

// ================= sweep: flat float4 grid-stride, ILP=4 (round-5 measured-best) =================
__device__ __forceinline__ void scan_one(float4 v, int e){
    float m = fmaxf(fmaxf(v.x,v.y), fmaxf(v.z,v.w));
    if (m > FLOOR_LOGIT){
        int row = e/21, chunk = e - row*21;
        if (chunk){                                   // chunk 0 = box quad, skip
            int b = row/NANCH, n = row - b*NANCH;
            int pb = b*NC + (chunk-1)*4;
            float vv[4] = {v.x, v.y, v.z, v.w};
            #pragma unroll
            for (int q = 0; q < 4; q++){
                if (vv[q] > FLOOR_LOGIT){
                    int p = pb + q;
                    int slot = atomicAdd(&g_cnt[p<<CSH], 1);
                    if (slot < CAP)
                        g_cand[p*CAP + slot] =
                            ((u64)(__float_as_uint(vv[q]) | 0x80000000u) << 32) | (u32)(0x7FFFFFFF - n);
                }
            }
        }
    }
}

__global__ __launch_bounds__(256) void k_scan(const float4* __restrict__ pred4){
    const int TOT = NROWS*21;                 // 12,889,800 float4s
    const int S = gridDim.x*blockDim.x;
    int e = blockIdx.x*blockDim.x + threadIdx.x;
    for (; e + 3*S < TOT; e += 4*S){
        float4 v0 = __ldg(pred4 + e);
        float4 v1 = __ldg(pred4 + e + S);
        float4 v2 = __ldg(pred4 + e + 2*S);
        float4 v3 = __ldg(pred4 + e + 3*S);
        scan_one(v0, e);
        scan_one(v1, e + S);
        scan_one(v2, e + 2*S);
        scan_one(v3, e + 3*S);
    }
    for (; e < TOT; e += S) scan_one(__ldg(pred4 + e), e);
}

// ================= exact radix-select machinery (direct atomics, tie-aware) =================
__device__ __forceinline__ void radix_scan_bins(int* bins, u32 prefix, int need,
                                                u32* sh_pref, int* sh_need, int* sh_tc){
    int tid = threadIdx.x;
    if (tid < 32){
        int c[8]; int lsum = 0;
        #pragma unroll
        for (int j = 0; j < 8; j++){ c[j] = bins[(tid<<3)+j]; lsum += c[j]; }
        int acc = lsum;
        #pragma unroll
        for (int off = 1; off < 32; off <<= 1){
            int t2 = __shfl_down_sync(0xFFFFFFFFu, acc, off);
            if (tid + off < 32) acc += t2;
        }
        int cum = acc - lsum;      // count with higher digit
        #pragma unroll
        for (int j = 7; j >= 0; j--){
            int nx = cum + c[j];
            if (cum < need && need <= nx){
                *sh_pref = (prefix << 8) | (u32)((tid<<3) + j);
                *sh_need = need - cum;
                *sh_tc   = c[j];
            }
            cum = nx;
        }
    }
}

// 32-bit radix select over register-resident keys.
// act_pos: restrict to keys whose hi top bit is set (positive scores).
template<int NK>
__device__ u32 radix_select32(const u64* key, bool lo_mode, u32 hi_match, bool act_pos, int T,
                              int* bins, u32* sh_pref, int* sh_need, int* sh_tc,
                              int* ret_need, int* ret_tc){
    u32 prefix = 0; int need = T, tc = 0;
    for (int pass = 0; pass < 4; pass++){
        const int shift = 24 - (pass<<3);
        for (int i = threadIdx.x; i < 256; i += blockDim.x) bins[i] = 0;
        __syncthreads();
        #pragma unroll
        for (int q = 0; q < NK; q++){
            u64 k = key[q];
            if (k){
                u32 hi = (u32)(k >> 32);
                u32 f  = lo_mode ? (u32)k : hi;
                bool ok = (!act_pos || (hi & 0x80000000u)) &&
                          (!lo_mode || hi == hi_match) &&
                          (pass == 0 || (f >> (shift+8)) == prefix);
                if (ok) atomicAdd(&bins[(f >> shift) & 255], 1);
            }
        }
        __syncthreads();
        radix_scan_bins(bins, prefix, need, sh_pref, sh_need, sh_tc);
        __syncthreads();
        prefix = *sh_pref; need = *sh_need; tc = *sh_tc;
        __syncthreads();
    }
    *ret_need = need; *ret_tc = tc;
    return prefix;
}

template<int NK>
__device__ u64 topk_thr(const u64* key, bool act_pos, int T,
                        int* bins, u32* shp, int* shn, int* sht){
    int need2, tc;
    u32 thr_hi = radix_select32<NK>(key, false, 0, act_pos, T, bins, shp, shn, sht, &need2, &tc);
    u32 thr_lo = 0;
    if (tc != need2){
        int d1, d2;
        thr_lo = radix_select32<NK>(key, true, thr_hi, act_pos, need2, bins, shp, shn, sht, &d1, &d2);
    }
    return ((u64)thr_hi << 32) | thr_lo;
}

// pair index q -> (i,j), i<j
__device__ __forceinline__ void pair_ij(int q, int* pi, int* pj){
    float qf = (float)q;
    int j = (int)((1.0f + sqrtf(1.0f + 8.0f*qf))*0.5f);
    while (j*(j-1)/2 > q) j--;
    while (j*(j+1)/2 <= q) j++;
    *pi = q - j*(j-1)/2;
    *pj = j;
}

// ================= per (image,class): top-100 + greedy NMS (256 threads) =================
__global__ __launch_bounds__(256) void k_classnms(const float* __restrict__ pred){
    const int p = blockIdx.x;
    const int tid = threadIdx.x;
    const int bimg = p / NC;

    __shared__ float2 s_dims[45];
    __shared__ int bins[256];
    __shared__ u32 sh_pref; __shared__ int sh_need, sh_tc, s_n, s_cnt;
    __shared__ u64 s_key[112];
    __shared__ int s_rankc[112];
    __shared__ float ssc[KMAX], sb0[KMAX], sb1[KMAX], sb2[KMAX], sb3[KMAX];
    __shared__ u32 supw[KMAX*4];
    __shared__ u32 s_keep[4];

    if (tid < 45){     // fp64-exact anchor dims (45 lanes once per block; measured OK)
        int lvl = tid/9, k = tid%9, ri = k/3, si = k%3;
        double side = 32.0 * (double)(1 << lvl);
        double area = side*side;
        double ratio = (ri==0) ? 0.5 : ((ri==1) ? 1.0 : 2.0);
        double scale = (si==0) ? 1.0 : ((si==1) ? 1.2599210498948732 : 1.5874010519681994);
        double ah = sqrt(area / ratio);
        double aw = area / ah;
        s_dims[tid] = make_float2((float)(scale*aw), (float)(scale*ah));
    }

    int cnt = g_cnt[p<<CSH];

    // exact fallback (block-uniform; never taken on this data, guards any data)
    if (cnt < KMAX || cnt > CAP){
        const int c = p % NC;
        const float* base = pred + (size_t)bimg*NANCH*NF + 4 + c;
        if (tid == 0) s_cnt = 0;
        __syncthreads();
        int loc = 0;
        for (int n = tid; n < NANCH; n += 256)
            if (sigmoidf_(base[(size_t)n*NF]) > SCORE_TH) loc++;
        atomicAdd(&s_cnt, loc);
        __syncthreads();
        int total = s_cnt;
        int T0 = min(total, KMAX);
        if (T0 == 0) cnt = 0;
        else {
            u64 lo = 0ull, hi = ~0ull;
            while (lo < hi){
                u64 mid = lo + ((hi - lo) >> 1) + 1ull;
                __syncthreads();
                if (tid == 0) s_cnt = 0;
                __syncthreads();
                int cc = 0;
                for (int n = tid; n < NANCH; n += 256){
                    float v = base[(size_t)n*NF];
                    if (sigmoidf_(v) > SCORE_TH){
                        u64 kk = ((u64)flip_f(__float_as_uint(v)) << 32) | (u32)(0x7FFFFFFF - n);
                        if (kk >= mid) cc++;
                    }
                }
                atomicAdd(&s_cnt, cc);
                __syncthreads();
                if (s_cnt >= T0) lo = mid; else hi = mid - 1;
            }
            __syncthreads();
            if (tid == 0) s_cnt = 0;
            __syncthreads();
            for (int n = tid; n < NANCH; n += 256){
                float v = base[(size_t)n*NF];
                if (sigmoidf_(v) > SCORE_TH){
                    u64 kk = ((u64)flip_f(__float_as_uint(v)) << 32) | (u32)(0x7FFFFFFF - n);
                    if (kk >= lo){
                        int sl = atomicAdd(&s_cnt, 1);
                        if (sl < CAP) g_cand[p*CAP + sl] = kk;
                    }
                }
            }
            cnt = T0;
        }
        __syncthreads();
    }

    const int T = min(cnt, KMAX);
    u64 key[2];
    #pragma unroll
    for (int q = 0; q < 2; q++){
        int s = tid + (q<<8);
        key[q] = (s < cnt) ? g_cand[p*CAP + s] : 0ull;
    }

    if (tid == 0) s_n = 0;
    if (tid < KMAX){ ssc[tid] = -1.0f; sb0[tid]=0.f; sb1[tid]=0.f; sb2[tid]=0.f; sb3[tid]=0.f; }
    if (tid < 112) s_rankc[tid] = 0;
    if (tid < KMAX*4 - 256){ supw[tid+256] = 0u; }
    supw[tid] = 0u;
    __syncthreads();

    u64 thr = 1ull;                              // cnt<=KMAX: take all nonzero keys
    if (cnt > KMAX) thr = topk_thr<2>(key, false, T, bins, &sh_pref, &sh_need, &sh_tc);

    #pragma unroll
    for (int q = 0; q < 2; q++){
        u64 k = key[q];
        if (k && k >= thr){
            int pos = atomicAdd(&s_n, 1);
            if (pos < 112) s_key[pos] = k;
        }
    }
    __syncthreads();
    const int mG = min(s_n, 112);

    // pair-parallel rank counting (keys distinct): rank = #{greater}
    const int PR = mG*(mG-1)/2;
    for (int q = tid; q < PR; q += 256){
        int i, j; pair_ij(q, &i, &j);
        if (s_key[i] < s_key[j]) atomicAdd(&s_rankc[i], 1);
        else                     atomicAdd(&s_rankc[j], 1);
    }
    __syncthreads();

    if (tid < mG){
        int rank = s_rankc[tid];
        if (rank < T){
            u64 k = s_key[tid];
            float logit = unflip_f((u32)(k >> 32));
            float sc = sigmoidf_(logit);
            int n = 0x7FFFFFFF - (int)(u32)(k & 0xFFFFFFFFull);
            int lvl = (n>=57600) + (n>=72000) + (n>=75600) + (n>=76500);
            int off = (lvl==0)?0 : (lvl==1)?57600 : (lvl==2)?72000 : (lvl==3)?75600 : 76500;
            int local = n - off;
            int k9   = local % 9;
            int cell = local / 9;
            int sh = 4 - lvl;
            int iy = (cell/5) >> sh;
            int jx = cell - iy*(5<<sh);
            float stridef = (float)(8<<lvl);
            float2 d = s_dims[lvl*9 + k9];
            float4 bp = __ldg((const float4*)pred + (size_t)(bimg*NANCH + n)*21);
            float cx = ((float)jx + 0.5f)*stridef;
            float cy = ((float)iy + 0.5f)*stridef;
            float x  = (bp.x*0.1f)*d.x + cx;
            float y  = (bp.y*0.1f)*d.y + cy;
            float ww = expf(bp.z*0.2f)*d.x;
            float hh = expf(bp.w*0.2f)*d.y;
            ssc[rank] = sc;
            sb0[rank] = x - ww*0.5f; sb1[rank] = y - hh*0.5f;
            sb2[rank] = x + ww*0.5f; sb3[rank] = y + hh*0.5f;
        }
    }
    __syncthreads();

    // pair-parallel suppression masks (32-bit atomicOr, native ATOMS)
    const int P = T*(T-1)/2;
    for (int q = tid; q < P; q += 256){
        int i, j; pair_ij(q, &i, &j);
        float ax=sb0[i], ay=sb1[i], az=sb2[i], aw=sb3[i];
        float bx=sb0[j], by=sb1[j], bz=sb2[j], bw=sb3[j];
        float ltx = fmaxf(ax,bx), lty = fmaxf(ay,by);
        float rbx = fminf(az,bz), rby = fminf(aw,bw);
        float w = fmaxf(rbx-ltx, 0.0f), h = fmaxf(rby-lty, 0.0f);
        float inter = w*h;
        float a1 = (az-ax)*(aw-ay);
        float a2 = (bz-bx)*(bw-by);
        float iou = inter / (a1 + a2 - inter + 1e-8f);
        if (iou > IOU_THR)
            atomicOr(&supw[i*4 + (j>>5)], 1u << (j & 31));
    }
    __syncthreads();

    // sequential greedy on 4x u32 masks (exact reference semantics)
    if (tid == 0){
        u32 keep[4];
        #pragma unroll
        for (int w = 0; w < 4; w++){
            int rem = T - w*32;
            keep[w] = (rem >= 32) ? 0xFFFFFFFFu : (rem <= 0 ? 0u : ((1u<<rem)-1u));
        }
        for (int i = 0; i < T; i++){
            if (keep[i>>5] & (1u << (i&31))){
                keep[0] &= ~supw[i*4+0]; keep[1] &= ~supw[i*4+1];
                keep[2] &= ~supw[i*4+2]; keep[3] &= ~supw[i*4+3];
            }
        }
        s_keep[0]=keep[0]; s_keep[1]=keep[1]; s_keep[2]=keep[2]; s_keep[3]=keep[3];
        g_cnt[p<<CSH] = 0;    // re-arm for next launch/replay
    }
    __syncthreads();
    if (tid < KMAX){
        bool kept = (tid < T) && (s_keep[tid>>5] & (1u << (tid&31)));
        g_cls_scores[p*KMAX + tid] = kept ? ssc[tid] : -1.0f;
        ((float4*)g_cls_boxes)[p*KMAX + tid] = make_float4(sb0[tid], sb1[tid], sb2[tid], sb3[tid]);
    }
}

// ================= per image merge: top-100 of 8000, write outputs =================
__global__ __launch_bounds__(256) void k_merge(float* __restrict__ out){
    const int b = blockIdx.x;
    const int tid = threadIdx.x;
    const int M = NC*KMAX;   // 8000

    u64 key[32];
    int npos_loc = 0;
    #pragma unroll
    for (int q = 0; q < 32; q++){
        int s = tid + (q<<8);
        u64 kk = 0ull;
        if (s < M){
            float sc = g_cls_scores[b*M + s];
            kk = ((u64)flip_f(__float_as_uint(sc)) << 32) | (u32)(0x7FFFFFFF - s);
            if (sc > 0.0f) npos_loc++;
        }
        key[q] = kk;
    }

    __shared__ int bins[256];
    __shared__ u32 sh_pref; __shared__ int sh_need, sh_tc;
    __shared__ int s_n, s_valid, s_npos;
    __shared__ u64 s_key[112];
    __shared__ int s_rankc[112];
    __shared__ u64 s_sorted[KMAX];

    if (tid == 0){ s_n = 0; s_valid = 0; s_npos = 0; }
    if (tid < 112) s_rankc[tid] = 0;
    __syncthreads();
    for (int o = 16; o; o >>= 1) npos_loc += __shfl_down_sync(0xFFFFFFFFu, npos_loc, o);
    if ((tid & 31) == 0 && npos_loc) atomicAdd(&s_npos, npos_loc);
    __syncthreads();
    const bool pos_only = (s_npos >= KMAX);  // true on real data; rare path stays exact

    u64 thr = topk_thr<32>(key, pos_only, KMAX, bins, &sh_pref, &sh_need, &sh_tc);

    #pragma unroll
    for (int q = 0; q < 32; q++){
        u64 k = key[q];
        bool act = k && (!pos_only || ((u32)(k>>32) & 0x80000000u));
        if (act && k >= thr){
            int pos = atomicAdd(&s_n, 1);
            if (pos < 112) s_key[pos] = k;
        }
    }
    __syncthreads();
    const int mG = min(s_n, 112);

    const int PR = mG*(mG-1)/2;
    for (int q = tid; q < PR; q += 256){
        int i, j; pair_ij(q, &i, &j);
        if (s_key[i] < s_key[j]) atomicAdd(&s_rankc[i], 1);
        else                     atomicAdd(&s_rankc[j], 1);
    }
    __syncthreads();
    if (tid < mG){
        int rank = s_rankc[tid];
        if (rank < KMAX) s_sorted[rank] = s_key[tid];
    }
    __syncthreads();

    if (tid < KMAX){
        u64 k = s_sorted[tid];
        float sc = unflip_f((u32)(k >> 32));
        int s = 0x7FFFFFFF - (int)(u32)(k & 0xFFFFFFFFull);
        bool good = sc > 0.0f;
        float4 bx = make_float4(0,0,0,0); float clsf = 0.0f;
        if (good){
            bx = ((const float4*)g_cls_boxes)[b*M + s];
            clsf = (float)(s / KMAX);
            atomicAdd(&s_valid, 1);
        }
        ((float4*)out)[b*KMAX + tid] = bx;                       // boxes  [0, 3200)
        out[BATCH*KMAX*4 + b*KMAX + tid] = fmaxf(sc, 0.0f);      // scores [3200, 4000)
        out[BATCH*KMAX*5 + b*KMAX + tid] = clsf;                 // classes[4000, 4800)
    }
    __syncthreads();
    if (tid == 0) out[BATCH*KMAX*6 + b] = (float)s_valid;        // valid  [4800, 4808)
}

extern "C" void kernel_launch(void* const* d_in, const int* in_sizes, int n_in,
                              void* d_out, int out_size){
    const float* pred = nullptr;
    const int PRED_SZ = BATCH*NANCH*NF;
    int best = -1;
    for (int i = 0; i < n_in; i++){
        if (in_sizes[i] == PRED_SZ){ pred = (const float*)d_in[i]; break; }
        if (best < 0 || in_sizes[i] > in_sizes[best]) best = i;
    }
    if (!pred) pred = (const float*)d_in[best < 0 ? 0 : best];

    float* out = (float*)d_out;
    (void)out_size;

    k_scan<<<2048, 256>>>((const float4*)pred);
    k_classnms<<<NPAIR, 256>>>(pred);
    k_merge<<<BATCH, 256>>>(out);
}

// round 10
// speedup vs baseline: 2.4315x; 1.2034x over previous
#include <cuda_runtime.h>
#include <stdint.h>
#include <math.h>

#define BATCH   8
#define NANCH   76725
#define NROWS   (BATCH*NANCH)
#define NC      80
#define NF      84
#define KMAX    100
#define CAP     512
#define NPAIR   (BATCH*NC)
#define FLOOR_LOGIT 2.8f
#define SCORE_TH 0.05f
#define IOU_THR 0.5f
#define CSH     5

typedef unsigned long long u64;
typedef unsigned int u32;

// scratch (BSS zero covers first call; classnms re-zeros g_cnt each launch)
__device__ int    g_cnt[NPAIR<<CSH];
__device__ u64    g_cand[NPAIR*CAP];        // (flip(logit)<<32) | (0x7FFFFFFF - n)
__device__ float  g_cls_scores[NPAIR*KMAX];
__device__ float  g_cls_boxes[NPAIR*KMAX*4];
__device__ float2 g_dims2[45];              // fp64-exact anchor dims (scan block 0 writes)

__device__ __forceinline__ float sigmoidf_(float x){ return 1.0f/(1.0f+expf(-x)); }
__device__ __forceinline__ u32 flip_f(u32 u){ return (u & 0x80000000u) ? ~u : (u | 0x80000000u); }
__device__ __forceinline__ float unflip_f(u32 u){
    return __uint_as_float((u & 0x80000000u) ? (u ^ 0x80000000u) : ~u);
}

// ================= sweep: flat float4 grid-stride, ILP=4 (measured best) =================
__device__ __forceinline__ void scan_one(float4 v, int e){
    float m = fmaxf(fmaxf(v.x,v.y), fmaxf(v.z,v.w));
    if (m > FLOOR_LOGIT){
        int row = e/21, chunk = e - row*21;
        if (chunk){                                   // chunk 0 = box quad, skip
            int b = row/NANCH, n = row - b*NANCH;
            int pb = b*NC + (chunk-1)*4;
            float vv[4] = {v.x, v.y, v.z, v.w};
            #pragma unroll
            for (int q = 0; q < 4; q++){
                if (vv[q] > FLOOR_LOGIT){
                    int p = pb + q;
                    int slot = atomicAdd(&g_cnt[p<<CSH], 1);
                    if (slot < CAP)
                        g_cand[p*CAP + slot] =
                            ((u64)(__float_as_uint(vv[q]) | 0x80000000u) << 32) | (u32)(0x7FFFFFFF - n);
                }
            }
        }
    }
}

__global__ __launch_bounds__(256) void k_scan(const float4* __restrict__ pred4){
    if (blockIdx.x == 0 && threadIdx.x < 45){   // fp64-exact dims, once per launch (mem-bound kernel: free)
        int t = threadIdx.x;
        int lvl = t/9, k = t%9, ri = k/3, si = k%3;
        double side = 32.0 * (double)(1 << lvl);
        double area = side*side;
        double ratio = (ri==0) ? 0.5 : ((ri==1) ? 1.0 : 2.0);
        double scale = (si==0) ? 1.0 : ((si==1) ? 1.2599210498948732 : 1.5874010519681994);
        double ah = sqrt(area / ratio);
        double aw = area / ah;
        g_dims2[t] = make_float2((float)(scale*aw), (float)(scale*ah));
    }
    const int TOT = NROWS*21;                 // 12,889,800 float4s
    const int S = gridDim.x*blockDim.x;
    int e = blockIdx.x*blockDim.x + threadIdx.x;
    for (; e + 3*S < TOT; e += 4*S){
        float4 v0 = __ldg(pred4 + e);
        float4 v1 = __ldg(pred4 + e + S);
        float4 v2 = __ldg(pred4 + e + 2*S);
        float4 v3 = __ldg(pred4 + e + 3*S);
        scan_one(v0, e);
        scan_one(v1, e + S);
        scan_one(v2, e + 2*S);
        scan_one(v3, e + 3*S);
    }
    for (; e < TOT; e += S) scan_one(__ldg(pred4 + e), e);
}

// ================= exact radix-select machinery (direct atomics, tie-aware) =================
__device__ __forceinline__ void radix_scan_bins(int* bins, u32 prefix, int need,
                                                u32* sh_pref, int* sh_need, int* sh_tc){
    int tid = threadIdx.x;
    if (tid < 32){
        int c[8]; int lsum = 0;
        #pragma unroll
        for (int j = 0; j < 8; j++){ c[j] = bins[(tid<<3)+j]; lsum += c[j]; }
        int acc = lsum;
        #pragma unroll
        for (int off = 1; off < 32; off <<= 1){
            int t2 = __shfl_down_sync(0xFFFFFFFFu, acc, off);
            if (tid + off < 32) acc += t2;
        }
        int cum = acc - lsum;      // count with higher digit
        #pragma unroll
        for (int j = 7; j >= 0; j--){
            int nx = cum + c[j];
            if (cum < need && need <= nx){
                *sh_pref = (prefix << 8) | (u32)((tid<<3) + j);
                *sh_need = need - cum;
                *sh_tc   = c[j];
            }
            cum = nx;
        }
    }
}

// 32-bit radix select over register-resident keys.
// act_pos: restrict to keys whose hi top bit is set (positive scores).
template<int NK>
__device__ u32 radix_select32(const u64* key, bool lo_mode, u32 hi_match, bool act_pos, int T,
                              int* bins, u32* sh_pref, int* sh_need, int* sh_tc,
                              int* ret_need, int* ret_tc){
    u32 prefix = 0; int need = T, tc = 0;
    for (int pass = 0; pass < 4; pass++){
        const int shift = 24 - (pass<<3);
        for (int i = threadIdx.x; i < 256; i += blockDim.x) bins[i] = 0;
        __syncthreads();
        #pragma unroll
        for (int q = 0; q < NK; q++){
            u64 k = key[q];
            if (k){
                u32 hi = (u32)(k >> 32);
                u32 f  = lo_mode ? (u32)k : hi;
                bool ok = (!act_pos || (hi & 0x80000000u)) &&
                          (!lo_mode || hi == hi_match) &&
                          (pass == 0 || (f >> (shift+8)) == prefix);
                if (ok) atomicAdd(&bins[(f >> shift) & 255], 1);
            }
        }
        __syncthreads();
        radix_scan_bins(bins, prefix, need, sh_pref, sh_need, sh_tc);
        __syncthreads();
        prefix = *sh_pref; need = *sh_need; tc = *sh_tc;
        __syncthreads();
    }
    *ret_need = need; *ret_tc = tc;
    return prefix;
}

template<int NK>
__device__ u64 topk_thr(const u64* key, bool act_pos, int T,
                        int* bins, u32* shp, int* shn, int* sht){
    int need2, tc;
    u32 thr_hi = radix_select32<NK>(key, false, 0, act_pos, T, bins, shp, shn, sht, &need2, &tc);
    u32 thr_lo = 0;
    if (tc != need2){
        int d1, d2;
        thr_lo = radix_select32<NK>(key, true, thr_hi, act_pos, need2, bins, shp, shn, sht, &d1, &d2);
    }
    return ((u64)thr_hi << 32) | thr_lo;
}

// pair index q -> (i,j), i<j (triangular; all lanes useful)
__device__ __forceinline__ void pair_ij(int q, int* pi, int* pj){
    float qf = (float)q;
    int j = (int)((1.0f + sqrtf(1.0f + 8.0f*qf))*0.5f);
    while (j*(j-1)/2 > q) j--;
    while (j*(j+1)/2 <= q) j++;
    *pi = q - j*(j-1)/2;
    *pj = j;
}

// ================= per (image,class): top-100 + greedy NMS (256 threads, lean) =================
__global__ __launch_bounds__(256) void k_classnms(const float* __restrict__ pred){
    const int p = blockIdx.x;
    const int tid = threadIdx.x;
    const int bimg = p / NC;

    __shared__ float2 s_dims[45];
    __shared__ int bins[256];
    __shared__ u32 sh_pref; __shared__ int sh_need, sh_tc, s_n, s_cnt;
    __shared__ u64 s_key[112];
    __shared__ float ssc[KMAX], sb0[KMAX], sb1[KMAX], sb2[KMAX], sb3[KMAX];
    __shared__ u32 supw[KMAX*4];
    __shared__ u32 s_keep[4];

    if (tid < 45) s_dims[tid] = g_dims2[tid];   // L2 hit, no FP64 here

    int cnt = g_cnt[p<<CSH];

    // exact fallback (block-uniform; never taken on this data, guards any data)
    if (cnt < KMAX || cnt > CAP){
        const int c = p % NC;
        const float* base = pred + (size_t)bimg*NANCH*NF + 4 + c;
        if (tid == 0) s_cnt = 0;
        __syncthreads();
        int loc = 0;
        for (int n = tid; n < NANCH; n += 256)
            if (sigmoidf_(base[(size_t)n*NF]) > SCORE_TH) loc++;
        atomicAdd(&s_cnt, loc);
        __syncthreads();
        int total = s_cnt;
        int T0 = min(total, KMAX);
        if (T0 == 0) cnt = 0;
        else {
            u64 lo = 0ull, hi = ~0ull;
            while (lo < hi){
                u64 mid = lo + ((hi - lo) >> 1) + 1ull;
                __syncthreads();
                if (tid == 0) s_cnt = 0;
                __syncthreads();
                int cc = 0;
                for (int n = tid; n < NANCH; n += 256){
                    float v = base[(size_t)n*NF];
                    if (sigmoidf_(v) > SCORE_TH){
                        u64 kk = ((u64)flip_f(__float_as_uint(v)) << 32) | (u32)(0x7FFFFFFF - n);
                        if (kk >= mid) cc++;
                    }
                }
                atomicAdd(&s_cnt, cc);
                __syncthreads();
                if (s_cnt >= T0) lo = mid; else hi = mid - 1;
            }
            __syncthreads();
            if (tid == 0) s_cnt = 0;
            __syncthreads();
            for (int n = tid; n < NANCH; n += 256){
                float v = base[(size_t)n*NF];
                if (sigmoidf_(v) > SCORE_TH){
                    u64 kk = ((u64)flip_f(__float_as_uint(v)) << 32) | (u32)(0x7FFFFFFF - n);
                    if (kk >= lo){
                        int sl = atomicAdd(&s_cnt, 1);
                        if (sl < CAP) g_cand[p*CAP + sl] = kk;
                    }
                }
            }
            cnt = T0;
        }
        __syncthreads();
    }

    const int T = min(cnt, KMAX);
    u64 key[2];
    #pragma unroll
    for (int q = 0; q < 2; q++){
        int s = tid + (q<<8);
        key[q] = (s < cnt) ? g_cand[p*CAP + s] : 0ull;
    }

    if (tid == 0) s_n = 0;
    if (tid < KMAX){ ssc[tid] = -1.0f; sb0[tid]=0.f; sb1[tid]=0.f; sb2[tid]=0.f; sb3[tid]=0.f; }
    if (tid < KMAX*4 - 256) supw[tid+256] = 0u;
    supw[tid] = 0u;
    __syncthreads();

    u64 thr = 1ull;                              // cnt<=KMAX: take all nonzero keys
    if (cnt > KMAX) thr = topk_thr<2>(key, false, T, bins, &sh_pref, &sh_need, &sh_tc);

    #pragma unroll
    for (int q = 0; q < 2; q++){
        u64 k = key[q];
        if (k && k >= thr){
            int pos = atomicAdd(&s_n, 1);
            if (pos < 112) s_key[pos] = k;
        }
    }
    __syncthreads();
    const int mG = min(s_n, 112);

    // per-thread rank (only winner threads active; keys distinct)
    if (tid < mG){
        u64 k = s_key[tid];
        int rank = 0;
        for (int jj = 0; jj < mG; jj++) rank += (s_key[jj] > k);
        if (rank < T){
            float logit = unflip_f((u32)(k >> 32));
            float sc = sigmoidf_(logit);
            int n = 0x7FFFFFFF - (int)(u32)(k & 0xFFFFFFFFull);
            int lvl = (n>=57600) + (n>=72000) + (n>=75600) + (n>=76500);
            int off = (lvl==0)?0 : (lvl==1)?57600 : (lvl==2)?72000 : (lvl==3)?75600 : 76500;
            int local = n - off;
            int k9   = local % 9;
            int cell = local / 9;
            int sh = 4 - lvl;
            int iy = (cell/5) >> sh;
            int jx = cell - iy*(5<<sh);
            float stridef = (float)(8<<lvl);
            float2 d = s_dims[lvl*9 + k9];
            float4 bp = __ldg((const float4*)pred + (size_t)(bimg*NANCH + n)*21);
            float cx = ((float)jx + 0.5f)*stridef;
            float cy = ((float)iy + 0.5f)*stridef;
            float x  = (bp.x*0.1f)*d.x + cx;
            float y  = (bp.y*0.1f)*d.y + cy;
            float ww = expf(bp.z*0.2f)*d.x;
            float hh = expf(bp.w*0.2f)*d.y;
            ssc[rank] = sc;
            sb0[rank] = x - ww*0.5f; sb1[rank] = y - hh*0.5f;
            sb2[rank] = x + ww*0.5f; sb3[rank] = y + hh*0.5f;
        }
    }
    __syncthreads();

    // pair-parallel suppression masks (triangular map, 32-bit atomicOr)
    const int P = T*(T-1)/2;
    for (int q = tid; q < P; q += 256){
        int i, j; pair_ij(q, &i, &j);
        float ax=sb0[i], ay=sb1[i], az=sb2[i], aw=sb3[i];
        float bx=sb0[j], by=sb1[j], bz=sb2[j], bw=sb3[j];
        float ltx = fmaxf(ax,bx), lty = fmaxf(ay,by);
        float rbx = fminf(az,bz), rby = fminf(aw,bw);
        float w = fmaxf(rbx-ltx, 0.0f), h = fmaxf(rby-lty, 0.0f);
        float inter = w*h;
        float a1 = (az-ax)*(aw-ay);
        float a2 = (bz-bx)*(bw-by);
        float iou = inter / (a1 + a2 - inter + 1e-8f);
        if (iou > IOU_THR)
            atomicOr(&supw[i*4 + (j>>5)], 1u << (j & 31));
    }
    __syncthreads();

    // sequential greedy on 4x u32 masks (exact reference semantics)
    if (tid == 0){
        u32 keep[4];
        #pragma unroll
        for (int w = 0; w < 4; w++){
            int rem = T - w*32;
            keep[w] = (rem >= 32) ? 0xFFFFFFFFu : (rem <= 0 ? 0u : ((1u<<rem)-1u));
        }
        for (int i = 0; i < T; i++){
            if (keep[i>>5] & (1u << (i&31))){
                keep[0] &= ~supw[i*4+0]; keep[1] &= ~supw[i*4+1];
                keep[2] &= ~supw[i*4+2]; keep[3] &= ~supw[i*4+3];
            }
        }
        s_keep[0]=keep[0]; s_keep[1]=keep[1]; s_keep[2]=keep[2]; s_keep[3]=keep[3];
        g_cnt[p<<CSH] = 0;    // re-arm for next launch/replay
    }
    __syncthreads();
    if (tid < KMAX){
        bool kept = (tid < T) && (s_keep[tid>>5] & (1u << (tid&31)));
        g_cls_scores[p*KMAX + tid] = kept ? ssc[tid] : -1.0f;
        ((float4*)g_cls_boxes)[p*KMAX + tid] = make_float4(sb0[tid], sb1[tid], sb2[tid], sb3[tid]);
    }
}

// ================= per image merge: top-100 of 8000, write outputs (512 threads) =================
__global__ __launch_bounds__(512) void k_merge(float* __restrict__ out){
    const int b = blockIdx.x;
    const int tid = threadIdx.x;
    const int M = NC*KMAX;   // 8000

    u64 key[16];
    int npos_loc = 0;
    #pragma unroll
    for (int q = 0; q < 16; q++){
        int s = tid + (q<<9);
        u64 kk = 0ull;
        if (s < M){
            float sc = g_cls_scores[b*M + s];
            kk = ((u64)flip_f(__float_as_uint(sc)) << 32) | (u32)(0x7FFFFFFF - s);
            if (sc > 0.0f) npos_loc++;
        }
        key[q] = kk;
    }

    __shared__ int bins[256];
    __shared__ u32 sh_pref; __shared__ int sh_need, sh_tc;
    __shared__ int s_n, s_valid, s_npos;
    __shared__ u64 s_key[112];
    __shared__ u64 s_sorted[KMAX];

    if (tid == 0){ s_n = 0; s_valid = 0; s_npos = 0; }
    if (tid < KMAX) s_sorted[tid] = 0ull;
    __syncthreads();
    for (int o = 16; o; o >>= 1) npos_loc += __shfl_down_sync(0xFFFFFFFFu, npos_loc, o);
    if ((tid & 31) == 0 && npos_loc) atomicAdd(&s_npos, npos_loc);
    __syncthreads();
    const bool pos_only = (s_npos >= KMAX);  // true on real data; rare path stays exact

    u64 thr = topk_thr<16>(key, pos_only, KMAX, bins, &sh_pref, &sh_need, &sh_tc);

    #pragma unroll
    for (int q = 0; q < 16; q++){
        u64 k = key[q];
        bool act = k && (!pos_only || ((u32)(k>>32) & 0x80000000u));
        if (act && k >= thr){
            int pos = atomicAdd(&s_n, 1);
            if (pos < 112) s_key[pos] = k;
        }
    }
    __syncthreads();
    const int mG = min(s_n, 112);

    if (tid < mG){
        u64 k = s_key[tid];
        int rank = 0;
        for (int jj = 0; jj < mG; jj++) rank += (s_key[jj] > k);
        if (rank < KMAX) s_sorted[rank] = k;
    }
    __syncthreads();

    if (tid < KMAX){
        u64 k = s_sorted[tid];
        float sc = unflip_f((u32)(k >> 32));
        int s = 0x7FFFFFFF - (int)(u32)(k & 0xFFFFFFFFull);
        bool good = (k != 0ull) && (sc > 0.0f);
        float4 bx = make_float4(0,0,0,0); float clsf = 0.0f;
        if (good){
            bx = ((const float4*)g_cls_boxes)[b*M + s];
            clsf = (float)(s / KMAX);
            atomicAdd(&s_valid, 1);
        }
        ((float4*)out)[b*KMAX + tid] = bx;                       // boxes  [0, 3200)
        out[BATCH*KMAX*4 + b*KMAX + tid] = good ? sc : 0.0f;     // scores [3200, 4000)
        out[BATCH*KMAX*5 + b*KMAX + tid] = clsf;                 // classes[4000, 4800)
    }
    __syncthreads();
    if (tid == 0) out[BATCH*KMAX*6 + b] = (float)s_valid;        // valid  [4800, 4808)
}

extern "C" void kernel_launch(void* const* d_in, const int* in_sizes, int n_in,
                              void* d_out, int out_size){
    const float* pred = nullptr;
    const int PRED_SZ = BATCH*NANCH*NF;
    int best = -1;
    for (int i = 0; i < n_in; i++){
        if (in_sizes[i] == PRED_SZ){ pred = (const float*)d_in[i]; break; }
        if (best < 0 || in_sizes[i] > in_sizes[best]) best = i;
    }
    if (!pred) pred = (const float*)d_in[best < 0 ? 0 : best];

    float* out = (float*)d_out;
    (void)out_size;

    k_scan<<<2048, 256>>>((const float4*)pred);
    k_classnms<<<NPAIR, 256>>>(pred);
    k_merge<<<BATCH, 512>>>(out);
}